// round 9
// baseline (speedup 1.0000x reference)
#include <cuda_runtime.h>
#include <cuda_fp16.h>
#include <cstdint>

// Problem constants
#define Bn 8
#define Hn 224
#define Wn 224
#define Cn 64
#define IN_DIM 576
#define RANKn 100
#define FILTERS 256
#define HW 50176            // 224*224
#define XTOT (Bn * Hn * Wn * Cn)
#define NCONVBLK (XTOT / 8 / 256)     // 3136 convert blocks

// GEMM tiling: CTA 128x128, 4 warps (2M x 2N), warp tile 64x64
#define CTA_M 128
#define CTA_N 128
#define BK 64                         // one full 3x3 tap (64 ch)
#define NT 128
#define KITERS (IN_DIM / BK)          // 9
#define STAGE_BYTES 32768             // A 16KB + B 16KB (fp16)
#define NSTAGE 3
#define SM_TOTAL (NSTAGE * STAGE_BYTES)  // 96KB -> 2 CTAs/SM

// Scratch (device globals; no allocation allowed)
__device__ float  g_M[RANKn * FILTERS];     // folded right factor [r][n]
__device__ __half g_Wh[FILTERS * IN_DIM];   // [n][k] fp16
__device__ __half g_xh[XTOT];               // x in fp16, same layout

// ---------------------------------------------------------------------------
__device__ __forceinline__ uint32_t smem_u32(const void* p) {
    uint32_t a;
    asm("{ .reg .u64 t; cvta.to.shared.u64 t, %1; cvt.u32.u64 %0, t; }"
        : "=r"(a) : "l"(p));
    return a;
}
#define CP_ASYNC_Z(d, s, sz) \
    asm volatile("cp.async.cg.shared.global [%0], [%1], 16, %2;" \
                 :: "r"(d), "l"(s), "r"(sz))
#define CP_ASYNC16(d, s) \
    asm volatile("cp.async.cg.shared.global [%0], [%1], 16;" :: "r"(d), "l"(s))
#define CP_COMMIT() asm volatile("cp.async.commit_group;" ::: "memory")
#define CP_WAIT(n)  asm volatile("cp.async.wait_group %0;" :: "n"(n) : "memory")

#define LDSM_X4(r0, r1, r2, r3, a) \
    asm volatile("ldmatrix.sync.aligned.m8n8.x4.shared.b16 {%0,%1,%2,%3}, [%4];" \
                 : "=r"(r0), "=r"(r1), "=r"(r2), "=r"(r3) : "r"(a))

#define MMA_F16(c, a, b0, b1)                                               \
    asm volatile("mma.sync.aligned.m16n8k16.row.col.f32.f16.f16.f32 "       \
                 "{%0,%1,%2,%3}, {%4,%5,%6,%7}, {%8,%9}, {%0,%1,%2,%3};"    \
                 : "+f"((c)[0]), "+f"((c)[1]), "+f"((c)[2]), "+f"((c)[3])   \
                 : "r"((a)[0]), "r"((a)[1]), "r"((a)[2]), "r"((a)[3]),      \
                   "r"(b0), "r"(b1))

// ---------------------------------------------------------------------------
// Prep 1 (fused): blocks [0, NCONVBLK) convert x -> fp16;
//                 blocks [NCONVBLK, ...) build g_M = right factor [100][256]
//   step 0: M = aux_Vt   step 1: M = l_t   step 2: M = s @ aux_Vtnp1
// ---------------------------------------------------------------------------
__global__ void prep1(const float* __restrict__ x,
                      const float* __restrict__ s,
                      const float* __restrict__ aux_Vt,
                      const float* __restrict__ l_t,
                      const float* __restrict__ aux_Vtnp1,
                      const int* __restrict__ step_p) {
    if (blockIdx.x < NCONVBLK) {
        int idx = blockIdx.x * 256 + threadIdx.x;   // one per 8 floats
        const float4* xp = reinterpret_cast<const float4*>(x) + idx * 2;
        float4 v0 = xp[0], v1 = xp[1];
        __half2 h[4];
        h[0] = __float22half2_rn(make_float2(v0.x, v0.y));
        h[1] = __float22half2_rn(make_float2(v0.z, v0.w));
        h[2] = __float22half2_rn(make_float2(v1.x, v1.y));
        h[3] = __float22half2_rn(make_float2(v1.z, v1.w));
        *reinterpret_cast<uint4*>(g_xh + (size_t)idx * 8) =
            *reinterpret_cast<uint4*>(h);
    } else {
        int idx = (blockIdx.x - NCONVBLK) * 256 + threadIdx.x;
        if (idx >= RANKn * FILTERS) return;
        int st = *step_p;
        float v;
        if (st == 0) v = aux_Vt[idx];
        else if (st == 1) v = l_t[idx];
        else {
            int r = idx / FILTERS, n = idx % FILTERS;
            float acc = 0.f;
            #pragma unroll 4
            for (int q = 0; q < RANKn; ++q)
                acc += s[r * RANKn + q] * aux_Vtnp1[q * FILTERS + n];
            v = acc;
        }
        g_M[idx] = v;
    }
}

// ---------------------------------------------------------------------------
// Prep 2: g_Wh[n][k] = fp16( sum_r U[k][r] * M[r][n] ), U per step.
// One block per n (256 blocks); M column cached in smem.
// ---------------------------------------------------------------------------
__global__ void build_Wh(const float* __restrict__ k_,
                         const float* __restrict__ aux_U,
                         const float* __restrict__ aux_Unp1,
                         const int* __restrict__ step_p) {
    __shared__ float Ms[RANKn];
    const int n = blockIdx.x;
    const int tid = threadIdx.x;
    if (tid < RANKn) Ms[tid] = g_M[tid * FILTERS + n];
    __syncthreads();
    int st = *step_p;
    const float* U = (st == 0) ? k_ : (st == 1) ? aux_U : aux_Unp1;
    for (int k = tid; k < IN_DIM; k += blockDim.x) {
        const float* ur = U + (size_t)k * RANKn;
        float acc = 0.f;
        #pragma unroll 4
        for (int r = 0; r < RANKn; ++r)
            acc += ur[r] * Ms[r];
        g_Wh[(size_t)n * IN_DIM + k] = __float2half_rn(acc);
    }
}

// ---------------------------------------------------------------------------
// Main: fp16 mma.sync implicit-GEMM conv
// CTA: 128 pixels x 128 filters; 4 warps (2M x 2N), warp tile 64x64.
// 3-stage cp.async ring, one barrier per K-iter, 2 CTAs/SM.
// ---------------------------------------------------------------------------
__global__ void __launch_bounds__(NT, 2)
conv_main(const float* __restrict__ bias_b,
          const float* __restrict__ bias_aux,
          const int* __restrict__ step_p,
          float* __restrict__ out) {
    extern __shared__ __align__(128) char smem[];
    const int tid  = threadIdx.x;
    const int lane = tid & 31;
    const int wid  = tid >> 5;
    const int mwarp = wid >> 1;       // 0..1
    const int nwarp = wid & 1;        // 0..1
    const int Mbase = blockIdx.x * CTA_M;
    const int Nbase = blockIdx.y * CTA_N;
    const uint32_t sb = smem_u32(smem);

    // Loader geometry: chunk j = tid&7, row group rA = tid>>3 (0..15)
    const int jA  = tid & 7;
    const int rA  = tid >> 3;
    uint32_t pc[8];                   // packed (b<<16 | h<<8 | w)
    #pragma unroll
    for (int l = 0; l < 8; ++l) {
        int p = Mbase + l * 16 + rA;
        int bi = p / HW;
        int rem = p - bi * HW;
        int h = rem / Wn;
        int w = rem - h * Wn;
        pc[l] = ((uint32_t)bi << 16) | ((uint32_t)h << 8) | (uint32_t)w;
    }

    float acc[4][8][4];
    #pragma unroll
    for (int mt = 0; mt < 4; ++mt)
        #pragma unroll
        for (int nt = 0; nt < 8; ++nt)
            #pragma unroll
            for (int q = 0; q < 4; ++q) acc[mt][nt][q] = 0.f;

    auto load_stage = [&](int ko) {
        const int stage = ko % NSTAGE;
        const int dh = ko / 3 - 1;
        const int dw = ko % 3 - 1;
        const uint32_t dA = sb + stage * STAGE_BYTES;
        #pragma unroll
        for (int l = 0; l < 8; ++l) {
            const int row = l * 16 + rA;
            const int hh = (int)((pc[l] >> 8) & 255u) + dh;
            const int ww = (int)(pc[l] & 255u) + dw;
            const int bi = (int)(pc[l] >> 16);
            const bool ok = ((unsigned)hh < (unsigned)Hn) &&
                            ((unsigned)ww < (unsigned)Wn);
            const __half* sp = ok
                ? g_xh + (((size_t)bi * Hn + hh) * Wn + ww) * Cn + jA * 8
                : g_xh;
            CP_ASYNC_Z(dA + row * 128 + ((jA ^ (row & 7)) << 4), sp, ok ? 16u : 0u);
        }
        const int k0 = ko * BK;
        const uint32_t dB = dA + 16384;
        #pragma unroll
        for (int l = 0; l < 8; ++l) {
            const int n = l * 16 + rA;
            const __half* bs = g_Wh + (size_t)(Nbase + n) * IN_DIM + k0 + jA * 8;
            CP_ASYNC16(dB + n * 128 + ((jA ^ (n & 7)) << 4), bs);
        }
    };

    // Fragment addressing
    const int m7  = lane & 7;
    const int khA = lane >> 4;               // A chunk parity
    const int khB = (lane >> 3) & 1;         // B chunk parity
    const uint32_t arow = (uint32_t)(mwarp * 64 + (lane & 15)) * 128;
    const uint32_t brow = (uint32_t)(nwarp * 64 + ((lane >> 4) << 3) + m7) * 128;
    uint32_t coffA[4], coffB[4];
    #pragma unroll
    for (int ks = 0; ks < 4; ++ks) {
        coffA[ks] = (uint32_t)(((ks * 2 + khA) ^ m7) << 4);
        coffB[ks] = (uint32_t)(((ks * 2 + khB) ^ m7) << 4);
    }

    load_stage(0); CP_COMMIT();
    load_stage(1); CP_COMMIT();

    #pragma unroll 3
    for (int ko = 0; ko < KITERS; ++ko) {
        if (ko < KITERS - 1) CP_WAIT(1);
        else                 CP_WAIT(0);
        __syncthreads();

        const uint32_t As = sb + (ko % NSTAGE) * STAGE_BYTES;
        const uint32_t Bs = As + 16384;

        // ks = 0 fragments FIRST (critical path), then kick next global stage
        uint32_t bf[4][4];
        #pragma unroll
        for (int np = 0; np < 4; ++np)
            LDSM_X4(bf[np][0], bf[np][1], bf[np][2], bf[np][3],
                    Bs + brow + np * (16 * 128) + coffB[0]);
        uint32_t a[4][4];
        #pragma unroll
        for (int mt = 0; mt < 4; ++mt)
            LDSM_X4(a[mt][0], a[mt][1], a[mt][2], a[mt][3],
                    As + arow + mt * (16 * 128) + coffA[0]);

        if (ko + 2 < KITERS) { load_stage(ko + 2); CP_COMMIT(); }

        #pragma unroll
        for (int mt = 0; mt < 4; ++mt)
            #pragma unroll
            for (int nt = 0; nt < 8; ++nt)
                MMA_F16(acc[mt][nt], a[mt],
                        bf[nt >> 1][(nt & 1) * 2],
                        bf[nt >> 1][(nt & 1) * 2 + 1]);

        #pragma unroll
        for (int ks = 1; ks < 4; ++ks) {
            #pragma unroll
            for (int np = 0; np < 4; ++np)
                LDSM_X4(bf[np][0], bf[np][1], bf[np][2], bf[np][3],
                        Bs + brow + np * (16 * 128) + coffB[ks]);
            #pragma unroll
            for (int mt = 0; mt < 4; ++mt)
                LDSM_X4(a[mt][0], a[mt][1], a[mt][2], a[mt][3],
                        As + arow + mt * (16 * 128) + coffA[ks]);
            #pragma unroll
            for (int mt = 0; mt < 4; ++mt)
                #pragma unroll
                for (int nt = 0; nt < 8; ++nt)
                    MMA_F16(acc[mt][nt], a[mt],
                            bf[nt >> 1][(nt & 1) * 2],
                            bf[nt >> 1][(nt & 1) * 2 + 1]);
        }
    }

    // Epilogue: bias + relu + store
    const float* bias = (*step_p == 2) ? bias_b : bias_aux;
    const int g  = lane >> 2;
    const int tq = lane & 3;
    #pragma unroll
    for (int mt = 0; mt < 4; ++mt) {
        const int r0 = Mbase + mwarp * 64 + mt * 16 + g;
        #pragma unroll
        for (int half = 0; half < 2; ++half) {
            const int r = r0 + half * 8;
            const int bi = r / HW;
            const int rr = r - bi * HW;
            const float* bp = bias + (size_t)rr * FILTERS;
            float* op = out + (size_t)r * FILTERS;
            #pragma unroll
            for (int nt = 0; nt < 8; ++nt) {
                const int col = Nbase + nwarp * 64 + nt * 8 + tq * 2;
                const float2 bv = *reinterpret_cast<const float2*>(bp + col);
                float2 o;
                o.x = fmaxf(acc[mt][nt][half * 2 + 0] + bv.x, 0.f);
                o.y = fmaxf(acc[mt][nt][half * 2 + 1] + bv.y, 0.f);
                *reinterpret_cast<float2*>(op + col) = o;
            }
        }
    }
}

// ---------------------------------------------------------------------------
// Inputs: 0:x 1:k 2:l_t 3:s 4:aux_U 5:aux_Unp1 6:aux_Vt 7:aux_Vtnp1
//         8:b 9:aux_b 10:step
// ---------------------------------------------------------------------------
extern "C" void kernel_launch(void* const* d_in, const int* in_sizes, int n_in,
                              void* d_out, int out_size) {
    const float* x         = (const float*)d_in[0];
    const float* k_        = (const float*)d_in[1];
    const float* l_t       = (const float*)d_in[2];
    const float* s         = (const float*)d_in[3];
    const float* aux_U     = (const float*)d_in[4];
    const float* aux_Unp1  = (const float*)d_in[5];
    const float* aux_Vt    = (const float*)d_in[6];
    const float* aux_Vtnp1 = (const float*)d_in[7];
    const float* bias_b    = (const float*)d_in[8];
    const float* bias_aux  = (const float*)d_in[9];
    const int*   step_p    = (const int*)d_in[10];
    float* out = (float*)d_out;

    const int nblk = NCONVBLK + (RANKn * FILTERS + 255) / 256;  // 3136 + 100
    prep1<<<nblk, 256>>>(x, s, aux_Vt, l_t, aux_Vtnp1, step_p);
    build_Wh<<<FILTERS, 192>>>(k_, aux_U, aux_Unp1, step_p);

    static bool cfg_done = false;
    if (!cfg_done) {
        cudaFuncSetAttribute(conv_main,
                             cudaFuncAttributeMaxDynamicSharedMemorySize, SM_TOTAL);
        cfg_done = true;
    }
    dim3 grid((Bn * Hn * Wn) / CTA_M, FILTERS / CTA_N);   // (3136, 2)
    conv_main<<<grid, NT, SM_TOTAL>>>(bias_b, bias_aux, step_p, out);
}

// round 10
// speedup vs baseline: 1.0325x; 1.0325x over previous
#include <cuda_runtime.h>
#include <cuda_fp16.h>
#include <cstdint>

// Problem constants
#define Bn 8
#define Hn 224
#define Wn 224
#define Cn 64
#define IN_DIM 576
#define RANKn 100
#define FILTERS 256
#define HW 50176            // 224*224
#define XTOT (Bn * Hn * Wn * Cn)
#define NCONVBLK (XTOT / 8 / 256)     // 3136 convert blocks

// GEMM tiling: CTA 128x128, 4 warps (2M x 2N), warp tile 64x64
#define CTA_M 128
#define CTA_N 128
#define BK 64                         // one full 3x3 tap (64 ch)
#define NT 128
#define KITERS (IN_DIM / BK)          // 9
#define STAGE_BYTES 32768             // A 16KB + B 16KB (fp16)
#define NSTAGE 3
#define SM_TOTAL (NSTAGE * STAGE_BYTES)  // 96KB -> 2 CTAs/SM

// Scratch (device globals; no allocation allowed)
__device__ float  g_M[RANKn * FILTERS];     // folded right factor [r][n]
__device__ __half g_Wh[FILTERS * IN_DIM];   // [n][k] fp16
__device__ __half g_xh[XTOT];               // x in fp16, same layout

// ---------------------------------------------------------------------------
__device__ __forceinline__ uint32_t smem_u32(const void* p) {
    uint32_t a;
    asm("{ .reg .u64 t; cvta.to.shared.u64 t, %1; cvt.u32.u64 %0, t; }"
        : "=r"(a) : "l"(p));
    return a;
}
#define CP_ASYNC_Z(d, s, sz) \
    asm volatile("cp.async.cg.shared.global [%0], [%1], 16, %2;" \
                 :: "r"(d), "l"(s), "r"(sz))
#define CP_ASYNC16(d, s) \
    asm volatile("cp.async.cg.shared.global [%0], [%1], 16;" :: "r"(d), "l"(s))
#define CP_COMMIT() asm volatile("cp.async.commit_group;" ::: "memory")
#define CP_WAIT(n)  asm volatile("cp.async.wait_group %0;" :: "n"(n) : "memory")

#define LDSM_X4(r0, r1, r2, r3, a) \
    asm volatile("ldmatrix.sync.aligned.m8n8.x4.shared.b16 {%0,%1,%2,%3}, [%4];" \
                 : "=r"(r0), "=r"(r1), "=r"(r2), "=r"(r3) : "r"(a))

#define MMA_F16(c, a, b0, b1)                                               \
    asm volatile("mma.sync.aligned.m16n8k16.row.col.f32.f16.f16.f32 "       \
                 "{%0,%1,%2,%3}, {%4,%5,%6,%7}, {%8,%9}, {%0,%1,%2,%3};"    \
                 : "+f"((c)[0]), "+f"((c)[1]), "+f"((c)[2]), "+f"((c)[3])   \
                 : "r"((a)[0]), "r"((a)[1]), "r"((a)[2]), "r"((a)[3]),      \
                   "r"(b0), "r"(b1))

// ---------------------------------------------------------------------------
// Prep 1 (fused): blocks [0, NCONVBLK) convert x -> fp16;
//                 blocks [NCONVBLK, ...) build g_M = right factor [100][256]
//   step 0: M = aux_Vt   step 1: M = l_t   step 2: M = s @ aux_Vtnp1
// ---------------------------------------------------------------------------
__global__ void prep1(const float* __restrict__ x,
                      const float* __restrict__ s,
                      const float* __restrict__ aux_Vt,
                      const float* __restrict__ l_t,
                      const float* __restrict__ aux_Vtnp1,
                      const int* __restrict__ step_p) {
    if (blockIdx.x < NCONVBLK) {
        int idx = blockIdx.x * 256 + threadIdx.x;   // one per 8 floats
        const float4* xp = reinterpret_cast<const float4*>(x) + idx * 2;
        float4 v0 = xp[0], v1 = xp[1];
        __half2 h[4];
        h[0] = __float22half2_rn(make_float2(v0.x, v0.y));
        h[1] = __float22half2_rn(make_float2(v0.z, v0.w));
        h[2] = __float22half2_rn(make_float2(v1.x, v1.y));
        h[3] = __float22half2_rn(make_float2(v1.z, v1.w));
        *reinterpret_cast<uint4*>(g_xh + (size_t)idx * 8) =
            *reinterpret_cast<uint4*>(h);
    } else {
        int idx = (blockIdx.x - NCONVBLK) * 256 + threadIdx.x;
        if (idx >= RANKn * FILTERS) return;
        int st = *step_p;
        float v;
        if (st == 0) v = aux_Vt[idx];
        else if (st == 1) v = l_t[idx];
        else {
            int r = idx / FILTERS, n = idx % FILTERS;
            float acc = 0.f;
            #pragma unroll 4
            for (int q = 0; q < RANKn; ++q)
                acc += s[r * RANKn + q] * aux_Vtnp1[q * FILTERS + n];
            v = acc;
        }
        g_M[idx] = v;
    }
}

// ---------------------------------------------------------------------------
// Prep 2: g_Wh[n][k] = fp16( sum_r U[k][r] * M[r][n] ), U per step.
// One block per n (256 blocks); M column cached in smem.
// ---------------------------------------------------------------------------
__global__ void build_Wh(const float* __restrict__ k_,
                         const float* __restrict__ aux_U,
                         const float* __restrict__ aux_Unp1,
                         const int* __restrict__ step_p) {
    __shared__ float Ms[RANKn];
    const int n = blockIdx.x;
    const int tid = threadIdx.x;
    if (tid < RANKn) Ms[tid] = g_M[tid * FILTERS + n];
    __syncthreads();
    int st = *step_p;
    const float* U = (st == 0) ? k_ : (st == 1) ? aux_U : aux_Unp1;
    for (int k = tid; k < IN_DIM; k += blockDim.x) {
        const float* ur = U + (size_t)k * RANKn;
        float acc = 0.f;
        #pragma unroll 4
        for (int r = 0; r < RANKn; ++r)
            acc += ur[r] * Ms[r];
        g_Wh[(size_t)n * IN_DIM + k] = __float2half_rn(acc);
    }
}

// ---------------------------------------------------------------------------
// Main: fp16 mma.sync implicit-GEMM conv  (R7 body — measured optimum)
// CTA: 128 pixels x 128 filters; 4 warps (2M x 2N), warp tile 64x64.
// 3-stage cp.async ring, one barrier per K-iter, 2 CTAs/SM.
// ---------------------------------------------------------------------------
__global__ void __launch_bounds__(NT, 2)
conv_main(const float* __restrict__ bias_b,
          const float* __restrict__ bias_aux,
          const int* __restrict__ step_p,
          float* __restrict__ out) {
    extern __shared__ __align__(128) char smem[];
    const int tid  = threadIdx.x;
    const int lane = tid & 31;
    const int wid  = tid >> 5;
    const int mwarp = wid >> 1;       // 0..1
    const int nwarp = wid & 1;        // 0..1
    const int Mbase = blockIdx.x * CTA_M;
    const int Nbase = blockIdx.y * CTA_N;
    const uint32_t sb = smem_u32(smem);

    // Loader geometry: chunk j = tid&7, row group rA = tid>>3 (0..15)
    const int jA  = tid & 7;
    const int rA  = tid >> 3;
    int hL[8], wL[8], bL[8];
    #pragma unroll
    for (int l = 0; l < 8; ++l) {
        int p = Mbase + l * 16 + rA;
        int bi = p / HW;
        int rem = p - bi * HW;
        hL[l] = rem / Wn;
        wL[l] = rem - hL[l] * Wn;
        bL[l] = bi;
    }

    float acc[4][8][4];
    #pragma unroll
    for (int mt = 0; mt < 4; ++mt)
        #pragma unroll
        for (int nt = 0; nt < 8; ++nt)
            #pragma unroll
            for (int q = 0; q < 4; ++q) acc[mt][nt][q] = 0.f;

    auto load_stage = [&](int ko) {
        const int stage = ko % NSTAGE;
        const int dh = ko / 3 - 1;
        const int dw = ko % 3 - 1;
        const uint32_t dA = sb + stage * STAGE_BYTES;
        #pragma unroll
        for (int l = 0; l < 8; ++l) {
            const int row = l * 16 + rA;
            const int hh = hL[l] + dh;
            const int ww = wL[l] + dw;
            const bool ok = ((unsigned)hh < (unsigned)Hn) &&
                            ((unsigned)ww < (unsigned)Wn);
            const __half* sp = ok
                ? g_xh + (((size_t)bL[l] * Hn + hh) * Wn + ww) * Cn + jA * 8
                : g_xh;
            CP_ASYNC_Z(dA + row * 128 + ((jA ^ (row & 7)) << 4), sp, ok ? 16u : 0u);
        }
        const int k0 = ko * BK;
        const uint32_t dB = dA + 16384;
        #pragma unroll
        for (int l = 0; l < 8; ++l) {
            const int n = l * 16 + rA;
            const __half* bs = g_Wh + (size_t)(Nbase + n) * IN_DIM + k0 + jA * 8;
            CP_ASYNC16(dB + n * 128 + ((jA ^ (n & 7)) << 4), bs);
        }
    };

    // Fragment addressing
    const int m7  = lane & 7;
    const int khA = lane >> 4;               // A chunk parity
    const int khB = (lane >> 3) & 1;         // B chunk parity
    const uint32_t arow = (uint32_t)(mwarp * 64 + (lane & 15)) * 128;
    const uint32_t brow = (uint32_t)(nwarp * 64 + ((lane >> 4) << 3) + m7) * 128;
    uint32_t coffA[4], coffB[4];
    #pragma unroll
    for (int ks = 0; ks < 4; ++ks) {
        coffA[ks] = (uint32_t)(((ks * 2 + khA) ^ m7) << 4);
        coffB[ks] = (uint32_t)(((ks * 2 + khB) ^ m7) << 4);
    }

    load_stage(0); CP_COMMIT();
    load_stage(1); CP_COMMIT();

    for (int ko = 0; ko < KITERS; ++ko) {
        if (ko < KITERS - 1) CP_WAIT(1);
        else                 CP_WAIT(0);
        __syncthreads();
        if (ko + 2 < KITERS) { load_stage(ko + 2); CP_COMMIT(); }

        const uint32_t As = sb + (ko % NSTAGE) * STAGE_BYTES;
        const uint32_t Bs = As + 16384;

        #pragma unroll
        for (int ks = 0; ks < 4; ++ks) {
            uint32_t bf[4][4];
            #pragma unroll
            for (int np = 0; np < 4; ++np)
                LDSM_X4(bf[np][0], bf[np][1], bf[np][2], bf[np][3],
                        Bs + brow + np * (16 * 128) + coffB[ks]);
            uint32_t a[4][4];
            #pragma unroll
            for (int mt = 0; mt < 4; ++mt)
                LDSM_X4(a[mt][0], a[mt][1], a[mt][2], a[mt][3],
                        As + arow + mt * (16 * 128) + coffA[ks]);
            #pragma unroll
            for (int mt = 0; mt < 4; ++mt)
                #pragma unroll
                for (int nt = 0; nt < 8; ++nt)
                    MMA_F16(acc[mt][nt], a[mt],
                            bf[nt >> 1][(nt & 1) * 2],
                            bf[nt >> 1][(nt & 1) * 2 + 1]);
        }
    }

    // Epilogue: bias + relu + store
    const float* bias = (*step_p == 2) ? bias_b : bias_aux;
    const int g  = lane >> 2;
    const int tq = lane & 3;
    #pragma unroll
    for (int mt = 0; mt < 4; ++mt) {
        const int r0 = Mbase + mwarp * 64 + mt * 16 + g;
        #pragma unroll
        for (int half = 0; half < 2; ++half) {
            const int r = r0 + half * 8;
            const int bi = r / HW;
            const int rr = r - bi * HW;
            const float* bp = bias + (size_t)rr * FILTERS;
            float* op = out + (size_t)r * FILTERS;
            #pragma unroll
            for (int nt = 0; nt < 8; ++nt) {
                const int col = Nbase + nwarp * 64 + nt * 8 + tq * 2;
                const float2 bv = *reinterpret_cast<const float2*>(bp + col);
                float2 o;
                o.x = fmaxf(acc[mt][nt][half * 2 + 0] + bv.x, 0.f);
                o.y = fmaxf(acc[mt][nt][half * 2 + 1] + bv.y, 0.f);
                *reinterpret_cast<float2*>(op + col) = o;
            }
        }
    }
}

// ---------------------------------------------------------------------------
// Inputs: 0:x 1:k 2:l_t 3:s 4:aux_U 5:aux_Unp1 6:aux_Vt 7:aux_Vtnp1
//         8:b 9:aux_b 10:step
// ---------------------------------------------------------------------------
extern "C" void kernel_launch(void* const* d_in, const int* in_sizes, int n_in,
                              void* d_out, int out_size) {
    const float* x         = (const float*)d_in[0];
    const float* k_        = (const float*)d_in[1];
    const float* l_t       = (const float*)d_in[2];
    const float* s         = (const float*)d_in[3];
    const float* aux_U     = (const float*)d_in[4];
    const float* aux_Unp1  = (const float*)d_in[5];
    const float* aux_Vt    = (const float*)d_in[6];
    const float* aux_Vtnp1 = (const float*)d_in[7];
    const float* bias_b    = (const float*)d_in[8];
    const float* bias_aux  = (const float*)d_in[9];
    const int*   step_p    = (const int*)d_in[10];
    float* out = (float*)d_out;

    const int nblk = NCONVBLK + (RANKn * FILTERS + 255) / 256;  // 3136 + 100
    prep1<<<nblk, 256>>>(x, s, aux_Vt, l_t, aux_Vtnp1, step_p);
    build_Wh<<<FILTERS, 192>>>(k_, aux_U, aux_Unp1, step_p);

    static bool cfg_done = false;
    if (!cfg_done) {
        cudaFuncSetAttribute(conv_main,
                             cudaFuncAttributeMaxDynamicSharedMemorySize, SM_TOTAL);
        cfg_done = true;
    }
    dim3 grid((Bn * Hn * Wn) / CTA_M, FILTERS / CTA_N);   // (3136, 2)
    conv_main<<<grid, NT, SM_TOTAL>>>(bias_b, bias_aux, step_p, out);
}